// round 17
// baseline (speedup 1.0000x reference)
#include <cuda_runtime.h>
#include <math.h>

#define NWAY 5
#define BB 4
#define CC 64
#define HWN 25
#define MS 125      // K_SHOT * h * w
#define MU 2500     // u * h * w
#define QQ 75
#define COLS 625    // NWAY * MS
#define MTOT 2625   // MS + MU
#define QROWS 1875  // 75 q * 25 rows (packed)
#define QROWP 1920  // padded to 15*128
#define CATP 2688   // padded cat columns (21*128)
#define NBLK 296    // 2 blocks/SM x 148 SMs

// ---------------- scratch (static device allocations only) ----------------
__device__ float g_unl_n[BB*MU*CC];              // [b][m][c]   row-major normalized unlabeled
__device__ float g_q_t[BB*CC*QROWP];             // [b][c][q*25+mq] transposed query (pads zero)
__device__ float g_cat_t[BB*NWAY*CC*CATP];       // [bw][c][j] = [sup(125) | compacted unl(cw)]
__device__ unsigned long long g_rowbest[BB*MU];  // per (b,m): packed (val,col) argmax
__device__ unsigned long long g_colbest[BB*COLS];// per (b,col): packed (val,m) argmax
__device__ unsigned long long g_rowq[BB*QROWP*NWAY]; // per (b,row,w): packed best over cols
__device__ int g_count[BB*NWAY];
__device__ int g_L[1];
__device__ unsigned g_tick_u, g_tick_q;          // work-queue tickets (reset in prep)

// monotone float ordering map (handles negatives exactly)
__device__ __forceinline__ unsigned fmap(float f){
    unsigned b=__float_as_uint(f);
    return (b&0x80000000u)? ~b : (b|0x80000000u);
}
__device__ __forceinline__ float funmap(unsigned u){
    return (u&0x80000000u)? __uint_as_float(u^0x80000000u) : __uint_as_float(~u);
}
// max-value, min-index-on-tie key (matches jnp first-occurrence argmax)
__device__ __forceinline__ unsigned long long packkey(float v, unsigned idx){
    return (((unsigned long long)fmap(v))<<32) | (unsigned long long)(0xFFFFFFFFu - idx);
}
// packed 2xFP32 FMA (Blackwell f32x2)
__device__ __forceinline__ void fma2(unsigned long long& acc, unsigned long long a, unsigned long long b){
    asm("fma.rn.f32x2 %0, %1, %2, %0;" : "+l"(acc) : "l"(a), "l"(b));
}
__device__ __forceinline__ unsigned long long splat2(float x){
    unsigned long long r;
    asm("mov.b64 %0, {%1, %1};" : "=l"(r) : "r"(__float_as_uint(x)));
    return r;
}
__device__ __forceinline__ void unpack2(unsigned long long v, float& lo, float& hi){
    unsigned a,b;
    asm("mov.b64 {%0, %1}, %2;" : "=r"(a), "=r"(b) : "l"(v));
    lo=__uint_as_float(a); hi=__uint_as_float(b);
}

// ---------------- K0: prep = init + all normalizations ----------------
__global__ void __launch_bounds__(256) k_prep(const float* __restrict__ sup,
                                              const float* __restrict__ unl,
                                              const float* __restrict__ qx,
                                              float* __restrict__ out, int out_size){
    int s = blockIdx.x;
    int tid = threadIdx.x;
    if (s >= 800){
        int i = (s-800)*256 + tid;
        const int stride = 16*256;
        for (int t=i;t<BB*MU;t+=stride) g_rowbest[t]=0ULL;
        for (int t=i;t<BB*COLS;t+=stride) g_colbest[t]=0ULL;
        if (i==0){ g_L[0]=0; g_tick_u=0u; g_tick_q=0u; }
        for (int t=i;t<out_size;t+=stride) out[t]=0.f;
        return;
    }
    __shared__ __align__(16) float tile[1664];   // 1600 used; tail pad for safe OOB reads
    __shared__ float inv[HWN];
    const float* in;
    if (s<100)      in = sup + (size_t)s*1600;
    else if (s<500) in = unl + (size_t)(s-100)*1600;
    else            in = qx  + (size_t)(s-500)*1600;
    {
        const float4* in4=(const float4*)in;
        float4* t4=(float4*)tile;
        for (int t=tid;t<400;t+=256) t4[t]=in4[t];
    }
    __syncthreads();
    {
        // parallel norm: 8 threads per hw (all 256 threads participate; hw>=25 discarded)
        int hw=tid>>3, k=tid&7;
        float a=0.f;
        #pragma unroll
        for (int c=k;c<CC;c+=8){ float v=tile[c*HWN+hw]; a=fmaf(v,v,a); }
        a += __shfl_xor_sync(0xffffffffu,a,4);
        a += __shfl_xor_sync(0xffffffffu,a,2);
        a += __shfl_xor_sync(0xffffffffu,a,1);
        if (k==0 && hw<HWN) inv[hw]=1.0f/fmaxf(sqrtf(a),1e-12f);
    }
    __syncthreads();
    if (s<100){
        int b=s/25, sk=s%25, w=sk/5, k=sk%5;
        // support columns live ONLY in g_cat_t (cols k*25..k*25+24 of way w)
        float* outc=g_cat_t+(size_t)(b*NWAY+w)*CC*CATP + k*25;
        for (int o=tid;o<1600;o+=256){
            int c=o/HWN,hw=o%HWN;
            outc[(size_t)c*CATP+hw]=tile[o]*inv[hw];
        }
    } else if (s<500){
        int t2=s-100; int b=t2/100,u=t2%100;
        float* outp=g_unl_n+(size_t)(b*MU+u*25)*CC;
        for (int o=tid;o<1600;o+=256){ int hw=o>>6,c=o&63; outp[o]=tile[c*HWN+hw]*inv[hw]; }
    } else {
        int t2=s-500; int b=t2/QQ, q=t2%QQ;
        float* outt=g_q_t+(size_t)b*CC*QROWP + q*25;
        for (int o=tid;o<1600;o+=256){ int c=o/HWN,hw=o%HWN; outt[(size_t)c*QROWP+hw]=tile[o]*inv[hw]; }
    }
}

// ---------------- K1: u2s GEMM (f32x2), persistent work-queue ---------------
// Ticket t in [0,400): b=t/100, w=(t/20)%5, mt=t%20.
// 256 threads: ci=tid&15 -> cols {ci*4..+3, 64+ci*4..+3}; mi=tid>>4 -> m rows mi*8..+7.
__global__ void __launch_bounds__(256,2) k_u2s(){
    __shared__ float4 s4[2048];                  // [c][32 f4] = 128 cols (32KB)
    __shared__ float4 u4[2048];                  // [c][32 f4] = 128 m   (32KB)
    __shared__ unsigned long long sm_col[128];
    __shared__ unsigned s_tick;
    int tid=threadIdx.x, lane=tid&31;
    int ci=tid&15, mi=tid>>4;

    for (;;){
        __syncthreads();                          // drain previous ticket's smem readers
        if (tid==0) s_tick = atomicAdd(&g_tick_u, 1u);
        __syncthreads();
        unsigned t = s_tick;
        if (t >= 400u) return;
        int b = (int)(t/100u), w = (int)((t/20u)%5u), mt = (int)(t%20u);
        int bw = b*NWAY + w;

        const float4* gs4=(const float4*)g_cat_t + (size_t)bw*(CC*CATP/4);
        #pragma unroll
        for (int tt=0;tt<8;++tt){
            int idx=tid+tt*256; int c=idx>>5, x=idx&31;
            s4[idx]=gs4[(size_t)c*(CATP/4)+x];
        }
        // stage u-tile transposed from g_unl_n: 2 threads per m-row
        {
            float* uf=(float*)u4;
            int m=tid>>1, half=tid&1;
            int mg=mt*128+m;
            const float4* src=(const float4*)(g_unl_n + (size_t)(b*MU + (mg<MU?mg:0))*CC) + half*8;
            #pragma unroll
            for (int i=0;i<8;++i){
                float4 v = src[i];
                if (mg>=MU) v=make_float4(0.f,0.f,0.f,0.f);
                int c=half*32+i*4;
                uf[(c+0)*128+m]=v.x;
                uf[(c+1)*128+m]=v.y;
                uf[(c+2)*128+m]=v.z;
                uf[(c+3)*128+m]=v.w;
            }
        }
        if (tid<128) sm_col[tid]=0ULL;
        __syncthreads();

        unsigned long long acc[8][4];                // [col j][row pair t]
        #pragma unroll
        for (int j=0;j<8;++j)
            #pragma unroll
            for (int tt=0;tt<4;++tt) acc[j][tt]=0ULL;

        #pragma unroll 2
        for (int c=0;c<64;++c){
            ulonglong2 bb0=*(const ulonglong2*)&u4[c*32 + mi*2];      // m mi*8..+3
            ulonglong2 bb1=*(const ulonglong2*)&u4[c*32 + mi*2 + 1];  // m mi*8+4..+7
            unsigned long long pb[4]={bb0.x,bb0.y,bb1.x,bb1.y};
            float4 x0=s4[c*32 + ci];         // cols ci*4..+3
            float4 x1=s4[c*32 + 16 + ci];    // cols 64+ci*4..+3
            float av[8]={x0.x,x0.y,x0.z,x0.w,x1.x,x1.y,x1.z,x1.w};
            #pragma unroll
            for (int j=0;j<8;++j){
                unsigned long long sa=splat2(av[j]);
                #pragma unroll
                for (int tt=0;tt<4;++tt) fma2(acc[j][tt],sa,pb[tt]);
            }
        }

        // epilogue: per-col keys via smem atomics; per-m keys in regs
        unsigned long long rkl[4], rkh[4];
        #pragma unroll
        for (int tt=0;tt<4;++tt){ rkl[tt]=0ULL; rkh[tt]=0ULL; }

        #pragma unroll
        for (int j=0;j<8;++j){
            int coll = (j<4)? ci*4+j : 64+ci*4+(j-4);
            bool vc = coll < MS;                      // cols 125..127 are garbage
            int colj = w*MS + coll;                   // global column id 0..624
            unsigned long long ck=0ULL;
            if (vc){
                #pragma unroll
                for (int tt=0;tt<4;++tt){
                    float lo,hi; unpack2(acc[j][tt],lo,hi);
                    unsigned long long kl=packkey(lo,(unsigned)colj);
                    unsigned long long kh=packkey(hi,(unsigned)colj);
                    if (kl>rkl[tt]) rkl[tt]=kl;
                    if (kh>rkh[tt]) rkh[tt]=kh;
                    int mglo = mt*128 + mi*8 + 2*tt;
                    if (mglo<MU){ unsigned long long c1=packkey(lo,(unsigned)mglo); if (c1>ck) ck=c1; }
                    if (mglo+1<MU){ unsigned long long c2=packkey(hi,(unsigned)(mglo+1)); if (c2>ck) ck=c2; }
                }
            }
            unsigned long long o=__shfl_xor_sync(0xffffffffu,ck,16);
            if (o>ck) ck=o;
            if (lane<16 && ck)
                atomicMax(&sm_col[(j<4)? lane*4+j : 64+lane*4+(j-4)], ck);
        }
        #pragma unroll
        for (int tt=0;tt<4;++tt){
            unsigned long long kl=rkl[tt], kh=rkh[tt];
            #pragma unroll
            for (int off=8;off>=1;off>>=1){
                unsigned long long o1=__shfl_xor_sync(0xffffffffu,kl,off);
                unsigned long long o2=__shfl_xor_sync(0xffffffffu,kh,off);
                if (o1>kl) kl=o1;
                if (o2>kh) kh=o2;
            }
            if ((lane&15)==0){
                int r0 = mt*128 + mi*8 + 2*tt;
                if (r0<MU && kl) atomicMax(&g_rowbest[(size_t)b*MU+r0], kl);
                if (r0+1<MU && kh) atomicMax(&g_rowbest[(size_t)b*MU+r0+1], kh);
            }
        }
        __syncthreads();
        if (tid<MS && sm_col[tid])
            atomicMax(&g_colbest[(size_t)b*COLS + w*MS + tid], sm_col[tid]);
    }
}

// ---------------- K2: fused compact + gather (per bw block) -----------------
__global__ void __launch_bounds__(512) k_cg(){
    int bw = blockIdx.x; int b = bw/NWAY, w = bw%NWAY;
    int tid = threadIdx.x, lane = tid&31, wid = tid>>5;   // 16 warps
    __shared__ int sel_s[640];                            // cw <= 625
    __shared__ int wsum[16], woff[16], sbase;
    __shared__ float tile[CC][65];
    if (tid==0) sbase=0;
    __syncthreads();
    for (int chunk=0; chunk<5; ++chunk){
        int m = chunk*512 + tid;
        bool flag = false;
        if (m < MU){
            unsigned long long rb = g_rowbest[b*MU+m];
            unsigned col = 0xFFFFFFFFu - (unsigned)(rb & 0xFFFFFFFFu);
            if ((int)(col/MS) == w){
                unsigned long long cb = g_colbest[b*COLS+col];
                unsigned mm = 0xFFFFFFFFu - (unsigned)(cb & 0xFFFFFFFFu);
                flag = (mm == (unsigned)m);
            }
        }
        unsigned bal = __ballot_sync(0xffffffffu, flag);
        if (lane==0) wsum[wid] = __popc(bal);
        __syncthreads();
        if (tid==0){
            int run=sbase;
            #pragma unroll
            for (int i=0;i<16;++i){ woff[i]=run; run+=wsum[i]; }
            sbase=run;
        }
        __syncthreads();
        if (flag){
            int pos = woff[wid] + __popc(bal & ((1u<<lane)-1u));
            sel_s[pos] = m;
        }
        __syncthreads();
    }
    int cw = sbase;
    if (tid==0){
        g_count[bw] = cw;
        atomicMax(&g_L[0], cw);
    }
    // Phase 2: gather
    const float* __restrict__ unl = g_unl_n + (size_t)b*MU*CC;
    float* __restrict__ cat = g_cat_t + (size_t)bw*CC*CATP + MS;
    for (int jb=0; jb<cw; jb+=64){
        int nj = min(64, cw-jb);
        for (int t=wid; t<nj; t+=16){
            int m = sel_s[jb+t];                             // broadcast per warp
            float2 v = ((const float2*)(unl + (size_t)m*CC))[lane];  // 256B coalesced
            tile[2*lane][t]   = v.x;
            tile[2*lane+1][t] = v.y;
        }
        __syncthreads();
        for (int o=tid; o<CC*64; o+=512){
            int c=o>>6, j=o&63;
            if (j<nj) cat[(size_t)c*CATP + jb + j] = tile[c][j];   // coalesced along j
        }
        __syncthreads();
    }
}

// ---------------- K3: query GEMM (f32x2), persistent work-queue -------------
// Ticket t in [0,300): qt=t%15, bw=t/15. rowq written with plain stores
// (each (row,w) owned by exactly one ticket).
__global__ void __launch_bounds__(256,2) k_qsim(){
    __shared__ float4 a4[2048];                 // q-rows: [c][32 f4] = 128 rows (32KB)
    __shared__ float4 v4[2048];                 // cols:   [c][32 f4] = 128 cols (32KB)
    __shared__ unsigned s_tick;
    int tid=threadIdx.x, lane=tid&31;
    int ci=tid&15, mi=tid>>4;

    for (;;){
        __syncthreads();                          // drain previous ticket's smem readers
        if (tid==0) s_tick = atomicAdd(&g_tick_q, 1u);
        __syncthreads();
        unsigned t = s_tick;
        if (t >= 300u) return;
        int qt = (int)(t%15u), bw = (int)(t/15u);
        int b=bw/NWAY, w=bw%NWAY;
        int cw=g_count[bw]; int wl=MS+cw;
        int nct=(wl+127)>>7;

        const float4* ga=(const float4*)g_q_t + (size_t)b*(CC*QROWP/4) + qt*32;
        #pragma unroll
        for (int tt=0;tt<8;++tt){
            int idx=tid+tt*256; int c=idx>>5, x=idx&31;
            a4[idx]=ga[(size_t)c*(QROWP/4)+x];
        }

        unsigned long long rkl[4], rkh[4];
        #pragma unroll
        for (int tt=0;tt<4;++tt){ rkl[tt]=0ULL; rkh[tt]=0ULL; }

        for (int ct=0; ct<nct; ++ct){
            if (ct) __syncthreads();            // drain previous tile's v4 readers
            const float4* gv=(const float4*)g_cat_t + (size_t)bw*(CC*CATP/4) + ct*32;
            #pragma unroll
            for (int tt=0;tt<8;++tt){
                int idx=tid+tt*256; int c=idx>>5, x=idx&31;
                v4[idx]=gv[(size_t)c*(CATP/4)+x];
            }
            __syncthreads();                    // also covers a4 on first iteration

            unsigned long long acc[8][4];
            #pragma unroll
            for (int j=0;j<8;++j)
                #pragma unroll
                for (int tt=0;tt<4;++tt) acc[j][tt]=0ULL;

            #pragma unroll 2
            for (int c=0;c<64;++c){
                ulonglong2 bb0=*(const ulonglong2*)&a4[c*32 + mi*2];      // rows mi*8..+3
                ulonglong2 bb1=*(const ulonglong2*)&a4[c*32 + mi*2 + 1];  // rows mi*8+4..+7
                unsigned long long pb[4]={bb0.x,bb0.y,bb1.x,bb1.y};
                float4 x0=v4[c*32 + ci];         // cols ci*4..+3
                float4 x1=v4[c*32 + 16 + ci];    // cols 64+ci*4..+3
                float av[8]={x0.x,x0.y,x0.z,x0.w,x1.x,x1.y,x1.z,x1.w};
                #pragma unroll
                for (int j=0;j<8;++j){
                    unsigned long long sa=splat2(av[j]);
                    #pragma unroll
                    for (int tt=0;tt<4;++tt) fma2(acc[j][tt],sa,pb[tt]);
                }
            }

            // accumulate per-thread col-max keys across tiles
            #pragma unroll
            for (int j=0;j<8;++j){
                int coll = (j<4)? ci*4+j : 64+ci*4+(j-4);
                int jg = ct*128 + coll;
                if (jg < wl){
                    unsigned gcol = (unsigned)(w*MTOT + jg);
                    #pragma unroll
                    for (int tt=0;tt<4;++tt){
                        float lo,hi; unpack2(acc[j][tt],lo,hi);
                        unsigned long long a1=packkey(lo,gcol);
                        unsigned long long a2=packkey(hi,gcol);
                        if (a1>rkl[tt]) rkl[tt]=a1;
                        if (a2>rkh[tt]) rkh[tt]=a2;
                    }
                }
            }
        }

        // final reduce over the 16 lanes of each half-warp; plain store
        #pragma unroll
        for (int tt=0;tt<4;++tt){
            unsigned long long kl=rkl[tt], kh=rkh[tt];
            #pragma unroll
            for (int off=8;off>=1;off>>=1){
                unsigned long long o1=__shfl_xor_sync(0xffffffffu,kl,off);
                unsigned long long o2=__shfl_xor_sync(0xffffffffu,kh,off);
                if (o1>kl) kl=o1;
                if (o2>kh) kh=o2;
            }
            if ((lane&15)==0){
                int r0 = qt*128 + mi*8 + 2*tt;
                if (r0<QROWS)   g_rowq[((size_t)b*QROWP + r0)*NWAY + w]   = kl;
                if (r0+1<QROWS) g_rowq[((size_t)b*QROWP + r0+1)*NWAY + w] = kh;
            }
        }
    }
}

// ---------------- K4: finish = recompute col-argmax + mutual mask + CE ------
__global__ void __launch_bounds__(256) k_fin(const int* __restrict__ qy,
                                             float* __restrict__ out){
    int q=blockIdx.x, b=blockIdx.y;
    int tid=threadIdx.x, lane=tid&31, wp=tid>>5;
    __shared__ float rmx_s[NWAY][32];
    __shared__ unsigned gcol_s[32];
    __shared__ float mask_s[32];
    __shared__ int cnt_s[NWAY+1];
    if (tid<NWAY) cnt_s[tid]=g_count[b*NWAY+tid];
    if (tid==NWAY) cnt_s[NWAY]=g_L[0];
    if (tid<32) mask_s[tid]=0.f;
    __syncthreads();
    // stage 1: per-row (mq) way-maxes and global best column
    if (wp==0 && lane<HWN){
        unsigned long long qb=0ULL;
        #pragma unroll
        for (int w=0;w<NWAY;++w){
            unsigned long long r = g_rowq[((size_t)b*QROWP + q*25 + lane)*NWAY + w];
            int cww=cnt_s[w];
            if (cww < cnt_s[NWAY]){
                // first all-zero pad column of this way: raw cos = 0.0, col id MS+cww
                unsigned long long pk = packkey(0.0f,(unsigned)(w*MTOT+MS+cww));
                if (pk>r) r=pk;
            }
            rmx_s[w][lane]=fmaf(funmap((unsigned)(r>>32)),0.5f,0.5f);
            if (r>qb) qb=r;
        }
        gcol_s[lane]=0xFFFFFFFFu - (unsigned)(qb & 0xFFFFFFFFu);
    }
    __syncthreads();
    // stage 2: per winning column, recompute argmax over mq (bitwise-identical chain)
    for (int t=wp; t<HWN; t+=8){
        unsigned gcol=gcol_s[t];
        int w_=(int)(gcol/MTOT), j_=(int)(gcol%MTOT);
        int amq=0;
        if (j_ < MS + cnt_s[w_]){
            float acc=0.f;
            const float* qp = g_q_t + (size_t)b*CC*QROWP + q*25 + lane;
            const float* cp = g_cat_t + (size_t)(b*NWAY+w_)*CC*CATP + j_;
            if (lane<HWN){
                #pragma unroll
                for (int c=0;c<CC;++c)
                    acc=fmaf(qp[(size_t)c*QROWP], cp[(size_t)c*CATP], acc);
            }
            unsigned long long k = (lane<HWN)? packkey(acc,(unsigned)lane) : 0ULL;
            #pragma unroll
            for (int off=16;off>=1;off>>=1){
                unsigned long long o=__shfl_xor_sync(0xffffffffu,k,off);
                if (o>k) k=o;
            }
            amq = (int)(0xFFFFFFFFu - (unsigned)(k & 0xFFFFFFFFu));
        }
        if (lane==0) mask_s[t] = (amq==t)?1.f:0.f;
    }
    __syncthreads();
    // stage 3: qv + cross-entropy
    if (wp==0){
        float qv[NWAY];
        #pragma unroll
        for (int w=0;w<NWAY;++w){
            float t = (lane<HWN) ? rmx_s[w][lane]*mask_s[lane] : 0.f;
            #pragma unroll
            for (int off=16;off>=1;off>>=1) t += __shfl_xor_sync(0xffffffffu,t,off);
            qv[w]=t;
        }
        if (lane==0){
            int y = qy[b*QQ+q];
            float mx=qv[0];
            #pragma unroll
            for (int w=1;w<NWAY;++w) mx=fmaxf(mx,qv[w]);
            float se=0.f;
            #pragma unroll
            for (int w=0;w<NWAY;++w) se += expf(qv[w]-mx);
            float li = mx + logf(se) - qv[y];
            atomicAdd(out, li*(1.0f/(float)(BB*QQ)));
        }
    }
}

// ---------------- launch ----------------
extern "C" void kernel_launch(void* const* d_in, const int* in_sizes, int n_in,
                              void* d_out, int out_size) {
    const float* sup = nullptr;
    const float* qx  = nullptr;
    const float* ux  = nullptr;
    const int*   qy  = nullptr;
    for (int i=0;i<n_in;++i){
        switch (in_sizes[i]){
            case 160000: sup = (const float*)d_in[i]; break; // support_xf
            case 480000: qx  = (const float*)d_in[i]; break; // query_xf
            case 640000: ux  = (const float*)d_in[i]; break; // unlabeled_xf
            case 300:    qy  = (const int*)d_in[i];   break; // query_y
            default: break;                                  // support_y unused
        }
    }
    float* out = (float*)d_out;
    k_prep<<<816,256>>>(sup, ux, qx, out, out_size);
    k_u2s<<<NBLK,256>>>();
    k_cg<<<BB*NWAY,512>>>();
    k_qsim<<<NBLK,256>>>();
    k_fin<<<dim3(QQ,BB),256>>>(qy, out);
}